// round 14
// baseline (speedup 1.0000x reference)
#include <cuda_runtime.h>
#include <cuda_bf16.h>
#include <math.h>
#include <stdint.h>

#define BATCH 2
#define TSEQ  2048
#define DM    1024
#define NH    16
#define DH    64
#define MTOT  (BATCH*TSEQ)   // 4096

// ---------------- scratch (device globals; no allocation allowed) ----------
__device__ __align__(16) __nv_bfloat16 g_qh[(size_t)BATCH*NH*TSEQ*DH];
__device__ __align__(16) __nv_bfloat16 g_ql[(size_t)BATCH*NH*TSEQ*DH];
__device__ __align__(16) __nv_bfloat16 g_kh[(size_t)BATCH*NH*TSEQ*DH];
__device__ __align__(16) __nv_bfloat16 g_kl[(size_t)BATCH*NH*TSEQ*DH];
__device__ __align__(16) __nv_bfloat16 g_vh[(size_t)BATCH*NH*TSEQ*DH];
__device__ __align__(16) __nv_bfloat16 g_vl[(size_t)BATCH*NH*TSEQ*DH];

__device__ __align__(16) __nv_bfloat16 g_xh[(size_t)MTOT*DM];
__device__ __align__(16) __nv_bfloat16 g_xl[(size_t)MTOT*DM];
__device__ __align__(16) __nv_bfloat16 g_wh[(size_t)3*DM*DM];  // [Wk;Wq;Wv] (q<-Wk swap!)
__device__ __align__(16) __nv_bfloat16 g_wl[(size_t)3*DM*DM];
__device__ __align__(16) __nv_bfloat16 g_ch[(size_t)MTOT*DM];
__device__ __align__(16) __nv_bfloat16 g_cl[(size_t)MTOT*DM];
__device__ __align__(16) __nv_bfloat16 g_woh[(size_t)DM*DM];
__device__ __align__(16) __nv_bfloat16 g_wol[(size_t)DM*DM];

// ---------------- helpers ---------------------------------------------------
__device__ __forceinline__ uint32_t smem_u32(const void* p) {
    uint32_t a;
    asm("{ .reg .u64 t; cvta.to.shared.u64 t, %1; cvt.u32.u64 %0, t; }"
        : "=r"(a) : "l"(p));
    return a;
}
__device__ __forceinline__ void cp_async16(uint32_t dst, const void* src) {
    asm volatile("cp.async.cg.shared.global [%0], [%1], 16;"
                 :: "r"(dst), "l"(src) : "memory");
}
__device__ __forceinline__ void cp_commit() {
    asm volatile("cp.async.commit_group;" ::: "memory");
}
__device__ __forceinline__ void cp_wait_all() {
    asm volatile("cp.async.wait_group 0;" ::: "memory");
}
__device__ __forceinline__ void cp_wait_1() {
    asm volatile("cp.async.wait_group 1;" ::: "memory");
}
__device__ __forceinline__ void ldsm4(uint32_t* r, uint32_t a) {
    asm volatile("ldmatrix.sync.aligned.m8n8.x4.shared.b16 {%0,%1,%2,%3}, [%4];"
                 : "=r"(r[0]), "=r"(r[1]), "=r"(r[2]), "=r"(r[3]) : "r"(a));
}
__device__ __forceinline__ void ldsm4t(uint32_t* r, uint32_t a) {
    asm volatile("ldmatrix.sync.aligned.m8n8.x4.trans.shared.b16 {%0,%1,%2,%3}, [%4];"
                 : "=r"(r[0]), "=r"(r[1]), "=r"(r[2]), "=r"(r[3]) : "r"(a));
}
__device__ __forceinline__ void mma_bf16(float* c, const uint32_t* a, const uint32_t* b) {
    asm volatile(
        "mma.sync.aligned.m16n8k16.row.col.f32.bf16.bf16.f32 "
        "{%0,%1,%2,%3}, {%4,%5,%6,%7}, {%8,%9}, {%0,%1,%2,%3};"
        : "+f"(c[0]), "+f"(c[1]), "+f"(c[2]), "+f"(c[3])
        : "r"(a[0]), "r"(a[1]), "r"(a[2]), "r"(a[3]), "r"(b[0]), "r"(b[1]));
}
__device__ __forceinline__ uint32_t cvt2(float v_hi, float v_lo) {
    uint32_t r;
    asm("cvt.rn.bf16x2.f32 %0, %1, %2;" : "=r"(r) : "f"(v_hi), "f"(v_lo));
    return r;
}
__device__ __forceinline__ void split2(float v0, float v1, uint32_t& hi, uint32_t& lo) {
    hi = cvt2(v1, v0);
    float h0 = __uint_as_float(hi << 16);
    float h1 = __uint_as_float(hi & 0xffff0000u);
    lo = cvt2(v1 - h1, v0 - h0);
}
__device__ __forceinline__ uint32_t swz(int row, int colb) {
    uint32_t off = row * 128 + colb;
    return off ^ ((off >> 3) & 0x70);
}

// ---------------- merged fp32 -> bf16 hi/lo split (5 segments) --------------
#define XB ((MTOT*DM/4)/256)     // 4096 blocks
#define WB ((DM*DM/4)/256)       // 1024 blocks

__global__ void __launch_bounds__(256) split5_kernel(
    const float* __restrict__ x,  const float* __restrict__ Wk,
    const float* __restrict__ Wq, const float* __restrict__ Wv,
    const float* __restrict__ Wo,
    __nv_bfloat16* __restrict__ xh, __nv_bfloat16* __restrict__ xl,
    __nv_bfloat16* __restrict__ wh, __nv_bfloat16* __restrict__ wl,
    __nv_bfloat16* __restrict__ woh, __nv_bfloat16* __restrict__ wol)
{
    int blk = blockIdx.x;
    const float* src;
    __nv_bfloat16 *dh, *dl;
    int i;
    if (blk < XB) {
        src = x; dh = xh; dl = xl;
        i = blk * 256 + threadIdx.x;
    } else {
        int wseg = (blk - XB) / WB;        // 0..3
        int wblk = (blk - XB) % WB;
        i = wblk * 256 + threadIdx.x;
        if (wseg == 0)      { src = Wk; dh = wh;            dl = wl; }
        else if (wseg == 1) { src = Wq; dh = wh + DM*DM;    dl = wl + DM*DM; }
        else if (wseg == 2) { src = Wv; dh = wh + 2*DM*DM;  dl = wl + 2*DM*DM; }
        else                { src = Wo; dh = woh;           dl = wol; }
    }
    float4 v = ((const float4*)src)[i];
    __nv_bfloat16 h[4], l[4];
    float f[4] = {v.x, v.y, v.z, v.w};
#pragma unroll
    for (int j = 0; j < 4; j++) {
        h[j] = __float2bfloat16(f[j]);
        l[j] = __float2bfloat16(f[j] - __bfloat162float(h[j]));
    }
    *(uint2*)(dh + (size_t)i*4) = *(uint2*)h;
    *(uint2*)(dl + (size_t)i*4) = *(uint2*)l;
}

// ---------------------------------------------------------------------------
// Split-bf16 GEMM on HMMA. 512 threads / 16 warps per CTA -> 4 warps per
// SMSP. Each warp owns a 32x32 sub-tile (2x4 m16n8 fragments, acc=32 regs).
// 3-stage cp.async pipeline.
// MODE 0: fused QKV -> bf16 hi/lo head-major (scale folded into q).
// MODE 1: fp32 out + bias.
// ---------------------------------------------------------------------------
#define GK       DM
#define BK       64
#define NCHUNK   (GK/BK)        // 16
#define TILE_B   (128*128)
#define BUF_B    (4*TILE_B)     // 64 KB
#define GEMM_SMEM (3*BUF_B)     // 196608
#define GTHREADS 512

template<int MODE>
__global__ void __launch_bounds__(GTHREADS, 1) mma_gemm(
    const __nv_bfloat16* __restrict__ Ah, const __nv_bfloat16* __restrict__ Al,
    const __nv_bfloat16* __restrict__ Bh, const __nv_bfloat16* __restrict__ Bl,
    __nv_bfloat16* __restrict__ qh, __nv_bfloat16* __restrict__ ql,
    __nv_bfloat16* __restrict__ kh, __nv_bfloat16* __restrict__ kl,
    __nv_bfloat16* __restrict__ vh, __nv_bfloat16* __restrict__ vl,
    float* __restrict__ out, const float* __restrict__ bias)
{
    extern __shared__ char smem[];
    const uint32_t sb = smem_u32(smem);
    const int tid  = threadIdx.x;
    const int lane = tid & 31;
    const int w    = tid >> 5;          // 0..15
    const int m0   = blockIdx.y * 128;
    const int n0   = blockIdx.x * 128;

    const __nv_bfloat16* srcs[4] = {Ah + (size_t)m0*GK, Al + (size_t)m0*GK,
                                    Bh + (size_t)n0*GK, Bl + (size_t)n0*GK};

    auto issue_chunk = [&](int buf, int k0) {
        uint32_t dbase = sb + buf * BUF_B;
#pragma unroll
        for (int t = 0; t < 4; t++) {
            const __nv_bfloat16* src = srcs[t] + k0;
            uint32_t tb = dbase + t * TILE_B;
#pragma unroll
            for (int r2 = 0; r2 < 2; r2++) {
                int id  = tid + GTHREADS * r2;   // 0..1023
                int row = id >> 3;
                int c16 = id & 7;
                cp_async16(tb + swz(row, c16 * 16), src + (size_t)row*GK + c16*8);
            }
        }
        cp_commit();
    };

    float acc[2][4][4];
#pragma unroll
    for (int mt = 0; mt < 2; mt++)
#pragma unroll
        for (int nt = 0; nt < 4; nt++)
#pragma unroll
            for (int e = 0; e < 4; e++) acc[mt][nt][e] = 0.0f;

    const int mr  = (w & 3) * 32;       // 4 m-groups
    const int nc0 = (w >> 2) * 32;      // 4 n-groups
    const int quad = lane >> 3;
    const int l7   = lane & 7;
    const int a_row_off = (quad & 1) * 8 + l7;
    const int a_col_off = (quad >> 1) * 16;
    const int b_row_off = (quad >> 1) * 8 + l7;
    const int b_col_off = (quad & 1) * 16;

    issue_chunk(0, 0);
    issue_chunk(1, BK);

    for (int c = 0; c < NCHUNK; c++) {
        if (c + 1 < NCHUNK) cp_wait_1(); else cp_wait_all();
        __syncthreads();
        if (c + 2 < NCHUNK) issue_chunk((c + 2) % 3, (c + 2) * BK);

        const uint32_t pAh = sb + (c % 3) * BUF_B;
        const uint32_t pAl = pAh + TILE_B;
        const uint32_t pBh = pAh + 2*TILE_B;
        const uint32_t pBl = pAh + 3*TILE_B;

#pragma unroll
        for (int ks = 0; ks < 4; ks++) {
            const int k0b = ks * 32;
            uint32_t aH[2][4], aL[2][4], bF[4][2], bL[4][2];
#pragma unroll
            for (int mt = 0; mt < 2; mt++) {
                int row = mr + mt*16 + a_row_off;
                ldsm4(aH[mt], pAh + swz(row, k0b + a_col_off));
                ldsm4(aL[mt], pAl + swz(row, k0b + a_col_off));
            }
#pragma unroll
            for (int ng = 0; ng < 2; ng++) {
                uint32_t t4[4];
                ldsm4(t4, pBh + swz(nc0 + ng*16 + b_row_off, k0b + b_col_off));
                bF[ng*2][0] = t4[0]; bF[ng*2][1] = t4[1];
                bF[ng*2+1][0] = t4[2]; bF[ng*2+1][1] = t4[3];
            }
#pragma unroll
            for (int ng = 0; ng < 2; ng++) {
                uint32_t t4[4];
                ldsm4(t4, pBl + swz(nc0 + ng*16 + b_row_off, k0b + b_col_off));
                bL[ng*2][0] = t4[0]; bL[ng*2][1] = t4[1];
                bL[ng*2+1][0] = t4[2]; bL[ng*2+1][1] = t4[3];
            }
            // hh
#pragma unroll
            for (int mt = 0; mt < 2; mt++)
#pragma unroll
                for (int nt = 0; nt < 4; nt++) mma_bf16(acc[mt][nt], aH[mt], bF[nt]);
            // lh
#pragma unroll
            for (int mt = 0; mt < 2; mt++)
#pragma unroll
                for (int nt = 0; nt < 4; nt++) mma_bf16(acc[mt][nt], aL[mt], bF[nt]);
            // hl
#pragma unroll
            for (int mt = 0; mt < 2; mt++)
#pragma unroll
                for (int nt = 0; nt < 4; nt++) mma_bf16(acc[mt][nt], aH[mt], bL[nt]);
        }
    }

    // ---- epilogue ----
#pragma unroll
    for (int mt = 0; mt < 2; mt++) {
#pragma unroll
        for (int half = 0; half < 2; half++) {
            const int m = m0 + mr + mt*16 + (lane >> 2) + half*8;
#pragma unroll
            for (int nt = 0; nt < 4; nt++) {
                const int n = n0 + nc0 + nt*8 + (lane & 3)*2;
                const float c0 = acc[mt][nt][half*2 + 0];
                const float c1 = acc[mt][nt][half*2 + 1];
                if (MODE == 0) {
                    const int bb  = m >> 11;
                    const int t   = m & 2047;
                    const int mat = n >> 10;
                    const int np  = n & 1023;
                    const float sc = (mat == 0) ? 0.125f : 1.0f;
                    uint32_t hi, lo;
                    split2(c0*sc, c1*sc, hi, lo);
                    __nv_bfloat16* ph = (mat == 0) ? qh : ((mat == 1) ? kh : vh);
                    __nv_bfloat16* pl = (mat == 0) ? ql : ((mat == 1) ? kl : vl);
                    size_t idx = ((size_t)(bb*NH + (np >> 6)) * TSEQ + t) * DH + (np & 63);
                    *(uint32_t*)(ph + idx) = hi;
                    *(uint32_t*)(pl + idx) = lo;
                } else {
                    float* p = out + (size_t)m * DM + n;
                    p[0] = c0 + __ldg(bias + n);
                    p[1] = c1 + __ldg(bias + n + 1);
                }
            }
        }
    }
}

// ---------------------------------------------------------------------------
// Causal flash attention on HMMA, split-bf16 — unchanged from round 11
// (3-stage KV pipeline; register-saturated, do not restructure blindly).
// ---------------------------------------------------------------------------
#define AKV   8192
#define ABUF  (4*AKV)                  // 32 KB per stage
#define AQ_OFF (3*ABUF)                // Q after 3 KV stages
#define ATTN_SMEM (3*ABUF + 2*16384)   // 131072

__global__ void __launch_bounds__(256, 1) attn_mma(
    const __nv_bfloat16* __restrict__ qh_g, const __nv_bfloat16* __restrict__ ql_g,
    const __nv_bfloat16* __restrict__ kh_g, const __nv_bfloat16* __restrict__ kl_g,
    const __nv_bfloat16* __restrict__ vh_g, const __nv_bfloat16* __restrict__ vl_g,
    __nv_bfloat16* __restrict__ ch_g, __nv_bfloat16* __restrict__ cl_g)
{
    extern __shared__ char smem[];
    const uint32_t sb = smem_u32(smem);
    const int tid  = threadIdx.x;
    const int lane = tid & 31;
    const int w    = tid >> 5;
    const int qt   = (TSEQ/128 - 1) - blockIdx.x;   // longest blocks first
    const int bh   = blockIdx.y;
    const int g    = lane >> 2;
    const int tig  = lane & 3;
    const int quad = lane >> 3;
    const int l7   = lane & 7;
    const int a_row  = (quad & 1) * 8 + l7;
    const int a_colb = (quad >> 1) * 16;
    const int b_row  = (quad >> 1) * 8 + l7;
    const int b_colb = (quad & 1) * 16;
    const int v_row  = (quad & 1) * 8 + l7;
    const int v_colb = (quad >> 1) * 16;

    const size_t base = (size_t)bh * TSEQ * DH;
    const int rowbase = qt * 128 + w * 16;

    auto issue_kv = [&](int buf, int key0) {
        uint32_t db = sb + buf * ABUF;
        const __nv_bfloat16* srcs[4] = {kh_g, kl_g, vh_g, vl_g};
#pragma unroll
        for (int t4 = 0; t4 < 4; t4++) {
#pragma unroll
            for (int r = 0; r < 2; r++) {
                int id  = tid + 256 * r;
                int row = id >> 3;
                int c16 = id & 7;
                cp_async16(db + t4*AKV + swz(row, c16*16),
                           srcs[t4] + base + (size_t)(key0 + row)*DH + c16*8);
            }
        }
        cp_commit();
    };

    const int NKT = 2*qt + 2;   // >= 2 always

    // prologue: group0 = Q + KV chunk 0; group1 = KV chunk 1
#pragma unroll
    for (int r = 0; r < 4; r++) {
        int id  = tid + 256 * r;
        int row = id >> 3;
        int c16 = id & 7;
        cp_async16(sb + AQ_OFF         + swz(row, c16*16),
                   qh_g + base + (size_t)(qt*128 + row)*DH + c16*8);
        cp_async16(sb + AQ_OFF + 16384 + swz(row, c16*16),
                   ql_g + base + (size_t)(qt*128 + row)*DH + c16*8);
    }
    issue_kv(0, 0);
    issue_kv(1, 64);

    float s[8][4], o[8][4];
    float m_i[2] = {-1e30f, -1e30f}, l_i[2] = {0.0f, 0.0f};
#pragma unroll
    for (int nt = 0; nt < 8; nt++)
#pragma unroll
        for (int e = 0; e < 4; e++) o[nt][e] = 0.0f;
    uint32_t qfh[4][4], qfl[4][4];

    for (int c = 0; c < NKT; c++) {
        if (c + 1 < NKT) cp_wait_1(); else cp_wait_all();
        __syncthreads();
        if (c == 0) {
#pragma unroll
            for (int ks = 0; ks < 4; ks++) {
                ldsm4(qfh[ks], sb + AQ_OFF         + swz(w*16 + a_row, ks*32 + a_colb));
                ldsm4(qfl[ks], sb + AQ_OFF + 16384 + swz(w*16 + a_row, ks*32 + a_colb));
            }
        }
        if (c + 2 < NKT) issue_kv((c + 2) % 3, (c + 2) * 64);

        const int key0 = c * 64;
        if (key0 <= rowbase + 15) {          // warp has unmasked work
            const uint32_t pb = sb + (c % 3) * ABUF;

            // ---- S = Qh*Kh + Ql*Kh + Qh*Kl ----
#pragma unroll
            for (int nt = 0; nt < 8; nt++)
#pragma unroll
                for (int e = 0; e < 4; e++) s[nt][e] = 0.0f;
#pragma unroll
            for (int ks = 0; ks < 4; ks++) {
                uint32_t bK[8][2], t4[4];
#pragma unroll
                for (int ng = 0; ng < 4; ng++) {
                    ldsm4(t4, pb + swz(ng*16 + b_row, ks*32 + b_colb));   // Kh
                    bK[ng*2][0] = t4[0]; bK[ng*2][1] = t4[1];
                    bK[ng*2+1][0] = t4[2]; bK[ng*2+1][1] = t4[3];
                }
#pragma unroll
                for (int nt = 0; nt < 8; nt++) mma_bf16(s[nt], qfh[ks], bK[nt]);
#pragma unroll
                for (int nt = 0; nt < 8; nt++) mma_bf16(s[nt], qfl[ks], bK[nt]);
#pragma unroll
                for (int ng = 0; ng < 4; ng++) {
                    ldsm4(t4, pb + AKV + swz(ng*16 + b_row, ks*32 + b_colb)); // Kl
                    bK[ng*2][0] = t4[0]; bK[ng*2][1] = t4[1];
                    bK[ng*2+1][0] = t4[2]; bK[ng*2+1][1] = t4[3];
                }
#pragma unroll
                for (int nt = 0; nt < 8; nt++) mma_bf16(s[nt], qfh[ks], bK[nt]);
            }

            // ---- causal mask (diagonal chunks only) ----
            if (key0 + 63 > rowbase) {
#pragma unroll
                for (int nt = 0; nt < 8; nt++) {
#pragma unroll
                    for (int e = 0; e < 4; e++) {
                        int col = key0 + nt*8 + 2*tig + (e & 1);
                        int row = rowbase + g + ((e >= 2) ? 8 : 0);
                        if (col > row) s[nt][e] = -1e30f;
                    }
                }
            }

            // ---- online softmax ----
            float rm0 = -1e30f, rm1 = -1e30f;
#pragma unroll
            for (int nt = 0; nt < 8; nt++) {
                rm0 = fmaxf(rm0, fmaxf(s[nt][0], s[nt][1]));
                rm1 = fmaxf(rm1, fmaxf(s[nt][2], s[nt][3]));
            }
            rm0 = fmaxf(rm0, __shfl_xor_sync(0xffffffffu, rm0, 1));
            rm0 = fmaxf(rm0, __shfl_xor_sync(0xffffffffu, rm0, 2));
            rm1 = fmaxf(rm1, __shfl_xor_sync(0xffffffffu, rm1, 1));
            rm1 = fmaxf(rm1, __shfl_xor_sync(0xffffffffu, rm1, 2));
            float mn0 = fmaxf(m_i[0], rm0), mn1 = fmaxf(m_i[1], rm1);
            float al0 = __expf(m_i[0] - mn0), al1 = __expf(m_i[1] - mn1);
            m_i[0] = mn0; m_i[1] = mn1;
            float rs0 = 0.0f, rs1 = 0.0f;
#pragma unroll
            for (int nt = 0; nt < 8; nt++) {
                s[nt][0] = __expf(s[nt][0] - mn0);
                s[nt][1] = __expf(s[nt][1] - mn0);
                s[nt][2] = __expf(s[nt][2] - mn1);
                s[nt][3] = __expf(s[nt][3] - mn1);
                rs0 += s[nt][0] + s[nt][1];
                rs1 += s[nt][2] + s[nt][3];
            }
            rs0 += __shfl_xor_sync(0xffffffffu, rs0, 1);
            rs0 += __shfl_xor_sync(0xffffffffu, rs0, 2);
            rs1 += __shfl_xor_sync(0xffffffffu, rs1, 1);
            rs1 += __shfl_xor_sync(0xffffffffu, rs1, 2);
            l_i[0] = l_i[0]*al0 + rs0;
            l_i[1] = l_i[1]*al1 + rs1;
#pragma unroll
            for (int nt = 0; nt < 8; nt++) {
                o[nt][0] *= al0; o[nt][1] *= al0;
                o[nt][2] *= al1; o[nt][3] *= al1;
            }

            // ---- O += Ph*Vh + Pl*Vh + Ph*Vl ----
#pragma unroll
            for (int ks = 0; ks < 4; ks++) {
                uint32_t ph[4], pl[4];
                split2(s[2*ks][0],   s[2*ks][1],   ph[0], pl[0]);
                split2(s[2*ks][2],   s[2*ks][3],   ph[1], pl[1]);
                split2(s[2*ks+1][0], s[2*ks+1][1], ph[2], pl[2]);
                split2(s[2*ks+1][2], s[2*ks+1][3], ph[3], pl[3]);
                uint32_t bV[8][2], t4[4];
#pragma unroll
                for (int ng = 0; ng < 4; ng++) {
                    ldsm4t(t4, pb + 2*AKV + swz(ks*16 + v_row, ng*32 + v_colb)); // Vh
                    bV[ng*2][0] = t4[0]; bV[ng*2][1] = t4[1];
                    bV[ng*2+1][0] = t4[2]; bV[ng*2+1][1] = t4[3];
                }
#pragma unroll
                for (int nt = 0; nt < 8; nt++) mma_bf16(o[nt], ph, bV[nt]);
#pragma unroll
                for (int nt = 0; nt < 8; nt++) mma_bf16(o[nt], pl, bV[nt]);
#pragma unroll
                for (int ng = 0; ng < 4; ng++) {
                    ldsm4t(t4, pb + 3*AKV + swz(ks*16 + v_row, ng*32 + v_colb)); // Vl
                    bV[ng*2][0] = t4[0]; bV[ng*2][1] = t4[1];
                    bV[ng*2+1][0] = t4[2]; bV[ng*2+1][1] = t4[3];
                }
#pragma unroll
                for (int nt = 0; nt < 8; nt++) mma_bf16(o[nt], ph, bV[nt]);
            }
        }
    }

    // ---- epilogue ----
    const int b_ = bh >> 4;
    const int h  = bh & 15;
    const float inv0 = 1.0f / l_i[0];
    const float inv1 = 1.0f / l_i[1];
    const int t0r = rowbase + g;
    const int t1r = rowbase + g + 8;
#pragma unroll
    for (int nt = 0; nt < 8; nt++) {
        const int col = h*64 + nt*8 + 2*tig;
        uint32_t hi, lo;
        split2(o[nt][0]*inv0, o[nt][1]*inv0, hi, lo);
        size_t i0 = ((size_t)(b_*TSEQ) + t0r) * DM + col;
        *(uint32_t*)(ch_g + i0) = hi;
        *(uint32_t*)(cl_g + i0) = lo;
        split2(o[nt][2]*inv1, o[nt][3]*inv1, hi, lo);
        size_t i1 = ((size_t)(b_*TSEQ) + t1r) * DM + col;
        *(uint32_t*)(ch_g + i1) = hi;
        *(uint32_t*)(cl_g + i1) = lo;
    }
}

// ---------------------------------------------------------------------------
extern "C" void kernel_launch(void* const* d_in, const int* in_sizes, int n_in,
                              void* d_out, int out_size)
{
    const float* x  = (const float*)d_in[0];
    const float* Wq = (const float*)d_in[1];
    const float* Wk = (const float*)d_in[2];
    const float* Wv = (const float*)d_in[3];
    const float* Wo = (const float*)d_in[4];
    const float* bo = (const float*)d_in[5];
    float* out = (float*)d_out;

    __nv_bfloat16 *qh, *ql, *kh, *kl, *vh, *vl;
    __nv_bfloat16 *xh, *xl, *wh, *wl, *ch, *cl, *woh, *wol;
    cudaGetSymbolAddress((void**)&qh,  g_qh);
    cudaGetSymbolAddress((void**)&ql,  g_ql);
    cudaGetSymbolAddress((void**)&kh,  g_kh);
    cudaGetSymbolAddress((void**)&kl,  g_kl);
    cudaGetSymbolAddress((void**)&vh,  g_vh);
    cudaGetSymbolAddress((void**)&vl,  g_vl);
    cudaGetSymbolAddress((void**)&xh,  g_xh);
    cudaGetSymbolAddress((void**)&xl,  g_xl);
    cudaGetSymbolAddress((void**)&wh,  g_wh);
    cudaGetSymbolAddress((void**)&wl,  g_wl);
    cudaGetSymbolAddress((void**)&ch,  g_ch);
    cudaGetSymbolAddress((void**)&cl,  g_cl);
    cudaGetSymbolAddress((void**)&woh, g_woh);
    cudaGetSymbolAddress((void**)&wol, g_wol);

    cudaFuncSetAttribute(mma_gemm<0>,
                         cudaFuncAttributeMaxDynamicSharedMemorySize, GEMM_SMEM);
    cudaFuncSetAttribute(mma_gemm<1>,
                         cudaFuncAttributeMaxDynamicSharedMemorySize, GEMM_SMEM);
    cudaFuncSetAttribute(attn_mma,
                         cudaFuncAttributeMaxDynamicSharedMemorySize, ATTN_SMEM);

    // single merged split launch (reference swaps names: q = x@Wk^T, k = x@Wq^T)
    split5_kernel<<<XB + 4*WB, 256>>>(x, Wk, Wq, Wv, Wo,
                                      xh, xl, wh, wl, woh, wol);

    // fused QKV projection (N=3072), bf16 hi/lo epilogue
    mma_gemm<0><<<dim3(3*DM/128, MTOT/128), GTHREADS, GEMM_SMEM>>>(
        xh, xl, wh, wl, qh, ql, kh, kl, vh, vl, nullptr, nullptr);

    attn_mma<<<dim3(TSEQ/128, BATCH*NH), 256, ATTN_SMEM>>>(
        qh, ql, kh, kl, vh, vl, ch, cl);

    mma_gemm<1><<<dim3(DM/128, MTOT/128), GTHREADS, GEMM_SMEM>>>(
        ch, cl, woh, wol, nullptr, nullptr, nullptr, nullptr, nullptr, nullptr,
        out, bo);
}

// round 15
// speedup vs baseline: 1.0440x; 1.0440x over previous
#include <cuda_runtime.h>
#include <cuda_bf16.h>
#include <math.h>
#include <stdint.h>

#define BATCH 2
#define TSEQ  2048
#define DM    1024
#define NH    16
#define DH    64
#define MTOT  (BATCH*TSEQ)   // 4096

// ---------------- scratch (device globals; no allocation allowed) ----------
__device__ __align__(16) __nv_bfloat16 g_qh[(size_t)BATCH*NH*TSEQ*DH];
__device__ __align__(16) __nv_bfloat16 g_ql[(size_t)BATCH*NH*TSEQ*DH];
__device__ __align__(16) __nv_bfloat16 g_kh[(size_t)BATCH*NH*TSEQ*DH];
__device__ __align__(16) __nv_bfloat16 g_kl[(size_t)BATCH*NH*TSEQ*DH];
__device__ __align__(16) __nv_bfloat16 g_vh[(size_t)BATCH*NH*TSEQ*DH];
__device__ __align__(16) __nv_bfloat16 g_vl[(size_t)BATCH*NH*TSEQ*DH];

__device__ __align__(16) __nv_bfloat16 g_xh[(size_t)MTOT*DM];
__device__ __align__(16) __nv_bfloat16 g_xl[(size_t)MTOT*DM];
__device__ __align__(16) __nv_bfloat16 g_wh[(size_t)3*DM*DM];  // [Wk;Wq;Wv] (q<-Wk swap!)
__device__ __align__(16) __nv_bfloat16 g_wl[(size_t)3*DM*DM];
__device__ __align__(16) __nv_bfloat16 g_ch[(size_t)MTOT*DM];
__device__ __align__(16) __nv_bfloat16 g_cl[(size_t)MTOT*DM];
__device__ __align__(16) __nv_bfloat16 g_woh[(size_t)DM*DM];
__device__ __align__(16) __nv_bfloat16 g_wol[(size_t)DM*DM];

// ---------------- helpers ---------------------------------------------------
__device__ __forceinline__ uint32_t smem_u32(const void* p) {
    uint32_t a;
    asm("{ .reg .u64 t; cvta.to.shared.u64 t, %1; cvt.u32.u64 %0, t; }"
        : "=r"(a) : "l"(p));
    return a;
}
__device__ __forceinline__ void cp_async16(uint32_t dst, const void* src) {
    asm volatile("cp.async.cg.shared.global [%0], [%1], 16;"
                 :: "r"(dst), "l"(src) : "memory");
}
__device__ __forceinline__ void cp_commit() {
    asm volatile("cp.async.commit_group;" ::: "memory");
}
__device__ __forceinline__ void cp_wait_all() {
    asm volatile("cp.async.wait_group 0;" ::: "memory");
}
__device__ __forceinline__ void cp_wait_1() {
    asm volatile("cp.async.wait_group 1;" ::: "memory");
}
__device__ __forceinline__ void ldsm4(uint32_t* r, uint32_t a) {
    asm volatile("ldmatrix.sync.aligned.m8n8.x4.shared.b16 {%0,%1,%2,%3}, [%4];"
                 : "=r"(r[0]), "=r"(r[1]), "=r"(r[2]), "=r"(r[3]) : "r"(a));
}
__device__ __forceinline__ void ldsm4t(uint32_t* r, uint32_t a) {
    asm volatile("ldmatrix.sync.aligned.m8n8.x4.trans.shared.b16 {%0,%1,%2,%3}, [%4];"
                 : "=r"(r[0]), "=r"(r[1]), "=r"(r[2]), "=r"(r[3]) : "r"(a));
}
__device__ __forceinline__ void mma_bf16(float* c, const uint32_t* a, const uint32_t* b) {
    asm volatile(
        "mma.sync.aligned.m16n8k16.row.col.f32.bf16.bf16.f32 "
        "{%0,%1,%2,%3}, {%4,%5,%6,%7}, {%8,%9}, {%0,%1,%2,%3};"
        : "+f"(c[0]), "+f"(c[1]), "+f"(c[2]), "+f"(c[3])
        : "r"(a[0]), "r"(a[1]), "r"(a[2]), "r"(a[3]), "r"(b[0]), "r"(b[1]));
}
__device__ __forceinline__ uint32_t cvt2(float v_hi, float v_lo) {
    uint32_t r;
    asm("cvt.rn.bf16x2.f32 %0, %1, %2;" : "=r"(r) : "f"(v_hi), "f"(v_lo));
    return r;
}
__device__ __forceinline__ void split2(float v0, float v1, uint32_t& hi, uint32_t& lo) {
    hi = cvt2(v1, v0);
    float h0 = __uint_as_float(hi << 16);
    float h1 = __uint_as_float(hi & 0xffff0000u);
    lo = cvt2(v1 - h1, v0 - h0);
}
__device__ __forceinline__ uint32_t swz(int row, int colb) {
    uint32_t off = row * 128 + colb;
    return off ^ ((off >> 3) & 0x70);
}

// ---------------- merged fp32 -> bf16 hi/lo split, coarsened ---------------
// Each thread processes 4 float4 (grid-stride within its segment block).
#define XB4 ((MTOT*DM/4)/1024)   // 1024 blocks for x (256 thr * 4 f4)
#define WB4 ((DM*DM/4)/1024)     // 256 blocks per weight

__global__ void __launch_bounds__(256) split5_kernel(
    const float* __restrict__ x,  const float* __restrict__ Wk,
    const float* __restrict__ Wq, const float* __restrict__ Wv,
    const float* __restrict__ Wo,
    __nv_bfloat16* __restrict__ xh, __nv_bfloat16* __restrict__ xl,
    __nv_bfloat16* __restrict__ wh, __nv_bfloat16* __restrict__ wl,
    __nv_bfloat16* __restrict__ woh, __nv_bfloat16* __restrict__ wol)
{
    int blk = blockIdx.x;
    const float* src;
    __nv_bfloat16 *dh, *dl;
    int base4;
    if (blk < XB4) {
        src = x; dh = xh; dl = xl;
        base4 = blk * 1024;
    } else {
        int wseg = (blk - XB4) / WB4;      // 0..3
        int wblk = (blk - XB4) % WB4;
        base4 = wblk * 1024;
        if (wseg == 0)      { src = Wk; dh = wh;            dl = wl; }
        else if (wseg == 1) { src = Wq; dh = wh + DM*DM;    dl = wl + DM*DM; }
        else if (wseg == 2) { src = Wv; dh = wh + 2*DM*DM;  dl = wl + 2*DM*DM; }
        else                { src = Wo; dh = woh;           dl = wol; }
    }
#pragma unroll
    for (int r = 0; r < 4; r++) {
        int i = base4 + threadIdx.x + r * 256;
        float4 v = ((const float4*)src)[i];
        __nv_bfloat16 h[4], l[4];
        float f[4] = {v.x, v.y, v.z, v.w};
#pragma unroll
        for (int j = 0; j < 4; j++) {
            h[j] = __float2bfloat16(f[j]);
            l[j] = __float2bfloat16(f[j] - __bfloat162float(h[j]));
        }
        *(uint2*)(dh + (size_t)i*4) = *(uint2*)h;
        *(uint2*)(dl + (size_t)i*4) = *(uint2*)l;
    }
}

// ---------------------------------------------------------------------------
// Split-bf16 GEMM on HMMA — round-11 config (best measured): 256 threads,
// 8 warps (32x64 tile each), 3-stage cp.async pipeline, wait_group 1.
// MODE 0: fused QKV -> bf16 hi/lo head-major (scale folded into q).
// MODE 1: fp32 out + bias (float2 stores).
// ---------------------------------------------------------------------------
#define GK       DM
#define BK       64
#define NCHUNK   (GK/BK)        // 16
#define TILE_B   (128*128)
#define BUF_B    (4*TILE_B)     // 64 KB
#define GEMM_SMEM (3*BUF_B)     // 196608

template<int MODE>
__global__ void __launch_bounds__(256, 1) mma_gemm(
    const __nv_bfloat16* __restrict__ Ah, const __nv_bfloat16* __restrict__ Al,
    const __nv_bfloat16* __restrict__ Bh, const __nv_bfloat16* __restrict__ Bl,
    __nv_bfloat16* __restrict__ qh, __nv_bfloat16* __restrict__ ql,
    __nv_bfloat16* __restrict__ kh, __nv_bfloat16* __restrict__ kl,
    __nv_bfloat16* __restrict__ vh, __nv_bfloat16* __restrict__ vl,
    float* __restrict__ out, const float* __restrict__ bias)
{
    extern __shared__ char smem[];
    const uint32_t sb = smem_u32(smem);
    const int tid  = threadIdx.x;
    const int lane = tid & 31;
    const int w    = tid >> 5;
    const int m0   = blockIdx.y * 128;
    const int n0   = blockIdx.x * 128;

    const __nv_bfloat16* srcs[4] = {Ah + (size_t)m0*GK, Al + (size_t)m0*GK,
                                    Bh + (size_t)n0*GK, Bl + (size_t)n0*GK};

    auto issue_chunk = [&](int buf, int k0) {
        uint32_t dbase = sb + buf * BUF_B;
#pragma unroll
        for (int t = 0; t < 4; t++) {
            const __nv_bfloat16* src = srcs[t] + k0;
            uint32_t tb = dbase + t * TILE_B;
#pragma unroll
            for (int r2 = 0; r2 < 4; r2++) {
                int id  = tid + 256 * r2;
                int row = id >> 3;
                int c16 = id & 7;
                cp_async16(tb + swz(row, c16 * 16), src + (size_t)row*GK + c16*8);
            }
        }
        cp_commit();
    };

    float acc[2][8][4];
#pragma unroll
    for (int mt = 0; mt < 2; mt++)
#pragma unroll
        for (int nt = 0; nt < 8; nt++)
#pragma unroll
            for (int e = 0; e < 4; e++) acc[mt][nt][e] = 0.0f;

    const int mr  = (w & 3) * 32;
    const int nc0 = (w >> 2) * 64;
    const int quad = lane >> 3;
    const int l7   = lane & 7;
    const int a_row_off = (quad & 1) * 8 + l7;
    const int a_col_off = (quad >> 1) * 16;
    const int b_row_off = (quad >> 1) * 8 + l7;
    const int b_col_off = (quad & 1) * 16;

    issue_chunk(0, 0);
    issue_chunk(1, BK);

    for (int c = 0; c < NCHUNK; c++) {
        if (c + 1 < NCHUNK) cp_wait_1(); else cp_wait_all();
        __syncthreads();
        if (c + 2 < NCHUNK) issue_chunk((c + 2) % 3, (c + 2) * BK);

        const uint32_t pAh = sb + (c % 3) * BUF_B;
        const uint32_t pAl = pAh + TILE_B;
        const uint32_t pBh = pAh + 2*TILE_B;
        const uint32_t pBl = pAh + 3*TILE_B;

#pragma unroll
        for (int ks = 0; ks < 4; ks++) {
            const int k0b = ks * 32;
            uint32_t aH[2][4], aL[2][4], bF[8][2], bL[8][2];
#pragma unroll
            for (int mt = 0; mt < 2; mt++) {
                int row = mr + mt*16 + a_row_off;
                ldsm4(aH[mt], pAh + swz(row, k0b + a_col_off));
                ldsm4(aL[mt], pAl + swz(row, k0b + a_col_off));
            }
#pragma unroll
            for (int ng = 0; ng < 4; ng++) {
                uint32_t t4[4];
                ldsm4(t4, pBh + swz(nc0 + ng*16 + b_row_off, k0b + b_col_off));
                bF[ng*2][0] = t4[0]; bF[ng*2][1] = t4[1];
                bF[ng*2+1][0] = t4[2]; bF[ng*2+1][1] = t4[3];
            }
#pragma unroll
            for (int ng = 0; ng < 4; ng++) {
                uint32_t t4[4];
                ldsm4(t4, pBl + swz(nc0 + ng*16 + b_row_off, k0b + b_col_off));
                bL[ng*2][0] = t4[0]; bL[ng*2][1] = t4[1];
                bL[ng*2+1][0] = t4[2]; bL[ng*2+1][1] = t4[3];
            }
            // hh
#pragma unroll
            for (int mt = 0; mt < 2; mt++)
#pragma unroll
                for (int nt = 0; nt < 8; nt++) mma_bf16(acc[mt][nt], aH[mt], bF[nt]);
            // lh
#pragma unroll
            for (int mt = 0; mt < 2; mt++)
#pragma unroll
                for (int nt = 0; nt < 8; nt++) mma_bf16(acc[mt][nt], aL[mt], bF[nt]);
            // hl
#pragma unroll
            for (int mt = 0; mt < 2; mt++)
#pragma unroll
                for (int nt = 0; nt < 8; nt++) mma_bf16(acc[mt][nt], aH[mt], bL[nt]);
        }
    }

    // ---- epilogue ----
#pragma unroll
    for (int mt = 0; mt < 2; mt++) {
#pragma unroll
        for (int half = 0; half < 2; half++) {
            const int m = m0 + mr + mt*16 + (lane >> 2) + half*8;
#pragma unroll
            for (int nt = 0; nt < 8; nt++) {
                const int n = n0 + nc0 + nt*8 + (lane & 3)*2;
                const float c0 = acc[mt][nt][half*2 + 0];
                const float c1 = acc[mt][nt][half*2 + 1];
                if (MODE == 0) {
                    const int bb  = m >> 11;
                    const int t   = m & 2047;
                    const int mat = n >> 10;
                    const int np  = n & 1023;
                    const float sc = (mat == 0) ? 0.125f : 1.0f;
                    uint32_t hi, lo;
                    split2(c0*sc, c1*sc, hi, lo);
                    __nv_bfloat16* ph = (mat == 0) ? qh : ((mat == 1) ? kh : vh);
                    __nv_bfloat16* pl = (mat == 0) ? ql : ((mat == 1) ? kl : vl);
                    size_t idx = ((size_t)(bb*NH + (np >> 6)) * TSEQ + t) * DH + (np & 63);
                    *(uint32_t*)(ph + idx) = hi;
                    *(uint32_t*)(pl + idx) = lo;
                } else {
                    const float2 bv = *(const float2*)(bias + n);
                    *(float2*)(out + (size_t)m * DM + n) =
                        make_float2(c0 + bv.x, c1 + bv.y);
                }
            }
        }
    }
}

// ---------------------------------------------------------------------------
// Causal flash attention on HMMA, split-bf16 — round-11 config unchanged.
// ---------------------------------------------------------------------------
#define AKV   8192
#define ABUF  (4*AKV)                  // 32 KB per stage
#define AQ_OFF (3*ABUF)                // Q after 3 KV stages
#define ATTN_SMEM (3*ABUF + 2*16384)   // 131072

__global__ void __launch_bounds__(256, 1) attn_mma(
    const __nv_bfloat16* __restrict__ qh_g, const __nv_bfloat16* __restrict__ ql_g,
    const __nv_bfloat16* __restrict__ kh_g, const __nv_bfloat16* __restrict__ kl_g,
    const __nv_bfloat16* __restrict__ vh_g, const __nv_bfloat16* __restrict__ vl_g,
    __nv_bfloat16* __restrict__ ch_g, __nv_bfloat16* __restrict__ cl_g)
{
    extern __shared__ char smem[];
    const uint32_t sb = smem_u32(smem);
    const int tid  = threadIdx.x;
    const int lane = tid & 31;
    const int w    = tid >> 5;
    const int qt   = (TSEQ/128 - 1) - blockIdx.x;   // longest blocks first
    const int bh   = blockIdx.y;
    const int g    = lane >> 2;
    const int tig  = lane & 3;
    const int quad = lane >> 3;
    const int l7   = lane & 7;
    const int a_row  = (quad & 1) * 8 + l7;
    const int a_colb = (quad >> 1) * 16;
    const int b_row  = (quad >> 1) * 8 + l7;
    const int b_colb = (quad & 1) * 16;
    const int v_row  = (quad & 1) * 8 + l7;
    const int v_colb = (quad >> 1) * 16;

    const size_t base = (size_t)bh * TSEQ * DH;
    const int rowbase = qt * 128 + w * 16;

    auto issue_kv = [&](int buf, int key0) {
        uint32_t db = sb + buf * ABUF;
        const __nv_bfloat16* srcs[4] = {kh_g, kl_g, vh_g, vl_g};
#pragma unroll
        for (int t4 = 0; t4 < 4; t4++) {
#pragma unroll
            for (int r = 0; r < 2; r++) {
                int id  = tid + 256 * r;
                int row = id >> 3;
                int c16 = id & 7;
                cp_async16(db + t4*AKV + swz(row, c16*16),
                           srcs[t4] + base + (size_t)(key0 + row)*DH + c16*8);
            }
        }
        cp_commit();
    };

    const int NKT = 2*qt + 2;   // >= 2 always

#pragma unroll
    for (int r = 0; r < 4; r++) {
        int id  = tid + 256 * r;
        int row = id >> 3;
        int c16 = id & 7;
        cp_async16(sb + AQ_OFF         + swz(row, c16*16),
                   qh_g + base + (size_t)(qt*128 + row)*DH + c16*8);
        cp_async16(sb + AQ_OFF + 16384 + swz(row, c16*16),
                   ql_g + base + (size_t)(qt*128 + row)*DH + c16*8);
    }
    issue_kv(0, 0);
    issue_kv(1, 64);

    float s[8][4], o[8][4];
    float m_i[2] = {-1e30f, -1e30f}, l_i[2] = {0.0f, 0.0f};
#pragma unroll
    for (int nt = 0; nt < 8; nt++)
#pragma unroll
        for (int e = 0; e < 4; e++) o[nt][e] = 0.0f;
    uint32_t qfh[4][4], qfl[4][4];

    for (int c = 0; c < NKT; c++) {
        if (c + 1 < NKT) cp_wait_1(); else cp_wait_all();
        __syncthreads();
        if (c == 0) {
#pragma unroll
            for (int ks = 0; ks < 4; ks++) {
                ldsm4(qfh[ks], sb + AQ_OFF         + swz(w*16 + a_row, ks*32 + a_colb));
                ldsm4(qfl[ks], sb + AQ_OFF + 16384 + swz(w*16 + a_row, ks*32 + a_colb));
            }
        }
        if (c + 2 < NKT) issue_kv((c + 2) % 3, (c + 2) * 64);

        const int key0 = c * 64;
        if (key0 <= rowbase + 15) {          // warp has unmasked work
            const uint32_t pb = sb + (c % 3) * ABUF;

            // ---- S = Qh*Kh + Ql*Kh + Qh*Kl ----
#pragma unroll
            for (int nt = 0; nt < 8; nt++)
#pragma unroll
                for (int e = 0; e < 4; e++) s[nt][e] = 0.0f;
#pragma unroll
            for (int ks = 0; ks < 4; ks++) {
                uint32_t bK[8][2], t4[4];
#pragma unroll
                for (int ng = 0; ng < 4; ng++) {
                    ldsm4(t4, pb + swz(ng*16 + b_row, ks*32 + b_colb));   // Kh
                    bK[ng*2][0] = t4[0]; bK[ng*2][1] = t4[1];
                    bK[ng*2+1][0] = t4[2]; bK[ng*2+1][1] = t4[3];
                }
#pragma unroll
                for (int nt = 0; nt < 8; nt++) mma_bf16(s[nt], qfh[ks], bK[nt]);
#pragma unroll
                for (int nt = 0; nt < 8; nt++) mma_bf16(s[nt], qfl[ks], bK[nt]);
#pragma unroll
                for (int ng = 0; ng < 4; ng++) {
                    ldsm4(t4, pb + AKV + swz(ng*16 + b_row, ks*32 + b_colb)); // Kl
                    bK[ng*2][0] = t4[0]; bK[ng*2][1] = t4[1];
                    bK[ng*2+1][0] = t4[2]; bK[ng*2+1][1] = t4[3];
                }
#pragma unroll
                for (int nt = 0; nt < 8; nt++) mma_bf16(s[nt], qfh[ks], bK[nt]);
            }

            // ---- causal mask (diagonal chunks only) ----
            if (key0 + 63 > rowbase) {
#pragma unroll
                for (int nt = 0; nt < 8; nt++) {
#pragma unroll
                    for (int e = 0; e < 4; e++) {
                        int col = key0 + nt*8 + 2*tig + (e & 1);
                        int row = rowbase + g + ((e >= 2) ? 8 : 0);
                        if (col > row) s[nt][e] = -1e30f;
                    }
                }
            }

            // ---- online softmax ----
            float rm0 = -1e30f, rm1 = -1e30f;
#pragma unroll
            for (int nt = 0; nt < 8; nt++) {
                rm0 = fmaxf(rm0, fmaxf(s[nt][0], s[nt][1]));
                rm1 = fmaxf(rm1, fmaxf(s[nt][2], s[nt][3]));
            }
            rm0 = fmaxf(rm0, __shfl_xor_sync(0xffffffffu, rm0, 1));
            rm0 = fmaxf(rm0, __shfl_xor_sync(0xffffffffu, rm0, 2));
            rm1 = fmaxf(rm1, __shfl_xor_sync(0xffffffffu, rm1, 1));
            rm1 = fmaxf(rm1, __shfl_xor_sync(0xffffffffu, rm1, 2));
            float mn0 = fmaxf(m_i[0], rm0), mn1 = fmaxf(m_i[1], rm1);
            float al0 = __expf(m_i[0] - mn0), al1 = __expf(m_i[1] - mn1);
            m_i[0] = mn0; m_i[1] = mn1;
            float rs0 = 0.0f, rs1 = 0.0f;
#pragma unroll
            for (int nt = 0; nt < 8; nt++) {
                s[nt][0] = __expf(s[nt][0] - mn0);
                s[nt][1] = __expf(s[nt][1] - mn0);
                s[nt][2] = __expf(s[nt][2] - mn1);
                s[nt][3] = __expf(s[nt][3] - mn1);
                rs0 += s[nt][0] + s[nt][1];
                rs1 += s[nt][2] + s[nt][3];
            }
            rs0 += __shfl_xor_sync(0xffffffffu, rs0, 1);
            rs0 += __shfl_xor_sync(0xffffffffu, rs0, 2);
            rs1 += __shfl_xor_sync(0xffffffffu, rs1, 1);
            rs1 += __shfl_xor_sync(0xffffffffu, rs1, 2);
            l_i[0] = l_i[0]*al0 + rs0;
            l_i[1] = l_i[1]*al1 + rs1;
#pragma unroll
            for (int nt = 0; nt < 8; nt++) {
                o[nt][0] *= al0; o[nt][1] *= al0;
                o[nt][2] *= al1; o[nt][3] *= al1;
            }

            // ---- O += Ph*Vh + Pl*Vh + Ph*Vl ----
#pragma unroll
            for (int ks = 0; ks < 4; ks++) {
                uint32_t ph[4], pl[4];
                split2(s[2*ks][0],   s[2*ks][1],   ph[0], pl[0]);
                split2(s[2*ks][2],   s[2*ks][3],   ph[1], pl[1]);
                split2(s[2*ks+1][0], s[2*ks+1][1], ph[2], pl[2]);
                split2(s[2*ks+1][2], s[2*ks+1][3], ph[3], pl[3]);
                uint32_t bV[8][2], t4[4];
#pragma unroll
                for (int ng = 0; ng < 4; ng++) {
                    ldsm4t(t4, pb + 2*AKV + swz(ks*16 + v_row, ng*32 + v_colb)); // Vh
                    bV[ng*2][0] = t4[0]; bV[ng*2][1] = t4[1];
                    bV[ng*2+1][0] = t4[2]; bV[ng*2+1][1] = t4[3];
                }
#pragma unroll
                for (int nt = 0; nt < 8; nt++) mma_bf16(o[nt], ph, bV[nt]);
#pragma unroll
                for (int nt = 0; nt < 8; nt++) mma_bf16(o[nt], pl, bV[nt]);
#pragma unroll
                for (int ng = 0; ng < 4; ng++) {
                    ldsm4t(t4, pb + 3*AKV + swz(ks*16 + v_row, ng*32 + v_colb)); // Vl
                    bV[ng*2][0] = t4[0]; bV[ng*2][1] = t4[1];
                    bV[ng*2+1][0] = t4[2]; bV[ng*2+1][1] = t4[3];
                }
#pragma unroll
                for (int nt = 0; nt < 8; nt++) mma_bf16(o[nt], ph, bV[nt]);
            }
        }
    }

    // ---- epilogue ----
    const int b_ = bh >> 4;
    const int h  = bh & 15;
    const float inv0 = 1.0f / l_i[0];
    const float inv1 = 1.0f / l_i[1];
    const int t0r = rowbase + g;
    const int t1r = rowbase + g + 8;
#pragma unroll
    for (int nt = 0; nt < 8; nt++) {
        const int col = h*64 + nt*8 + 2*tig;
        uint32_t hi, lo;
        split2(o[nt][0]*inv0, o[nt][1]*inv0, hi, lo);
        size_t i0 = ((size_t)(b_*TSEQ) + t0r) * DM + col;
        *(uint32_t*)(ch_g + i0) = hi;
        *(uint32_t*)(cl_g + i0) = lo;
        split2(o[nt][2]*inv1, o[nt][3]*inv1, hi, lo);
        size_t i1 = ((size_t)(b_*TSEQ) + t1r) * DM + col;
        *(uint32_t*)(ch_g + i1) = hi;
        *(uint32_t*)(cl_g + i1) = lo;
    }
}

// ---------------------------------------------------------------------------
extern "C" void kernel_launch(void* const* d_in, const int* in_sizes, int n_in,
                              void* d_out, int out_size)
{
    const float* x  = (const float*)d_in[0];
    const float* Wq = (const float*)d_in[1];
    const float* Wk = (const float*)d_in[2];
    const float* Wv = (const float*)d_in[3];
    const float* Wo = (const float*)d_in[4];
    const float* bo = (const float*)d_in[5];
    float* out = (float*)d_out;

    __nv_bfloat16 *qh, *ql, *kh, *kl, *vh, *vl;
    __nv_bfloat16 *xh, *xl, *wh, *wl, *ch, *cl, *woh, *wol;
    cudaGetSymbolAddress((void**)&qh,  g_qh);
    cudaGetSymbolAddress((void**)&ql,  g_ql);
    cudaGetSymbolAddress((void**)&kh,  g_kh);
    cudaGetSymbolAddress((void**)&kl,  g_kl);
    cudaGetSymbolAddress((void**)&vh,  g_vh);
    cudaGetSymbolAddress((void**)&vl,  g_vl);
    cudaGetSymbolAddress((void**)&xh,  g_xh);
    cudaGetSymbolAddress((void**)&xl,  g_xl);
    cudaGetSymbolAddress((void**)&wh,  g_wh);
    cudaGetSymbolAddress((void**)&wl,  g_wl);
    cudaGetSymbolAddress((void**)&ch,  g_ch);
    cudaGetSymbolAddress((void**)&cl,  g_cl);
    cudaGetSymbolAddress((void**)&woh, g_woh);
    cudaGetSymbolAddress((void**)&wol, g_wol);

    cudaFuncSetAttribute(mma_gemm<0>,
                         cudaFuncAttributeMaxDynamicSharedMemorySize, GEMM_SMEM);
    cudaFuncSetAttribute(mma_gemm<1>,
                         cudaFuncAttributeMaxDynamicSharedMemorySize, GEMM_SMEM);
    cudaFuncSetAttribute(attn_mma,
                         cudaFuncAttributeMaxDynamicSharedMemorySize, ATTN_SMEM);

    // single merged split launch (reference swaps names: q = x@Wk^T, k = x@Wq^T)
    split5_kernel<<<XB4 + 4*WB4, 256>>>(x, Wk, Wq, Wv, Wo,
                                        xh, xl, wh, wl, woh, wol);

    // fused QKV projection (N=3072), bf16 hi/lo epilogue
    mma_gemm<0><<<dim3(3*DM/128, MTOT/128), 256, GEMM_SMEM>>>(
        xh, xl, wh, wl, qh, ql, kh, kl, vh, vl, nullptr, nullptr);

    attn_mma<<<dim3(TSEQ/128, BATCH*NH), 256, ATTN_SMEM>>>(
        qh, ql, kh, kl, vh, vl, ch, cl);

    mma_gemm<1><<<dim3(DM/128, MTOT/128), 256, GEMM_SMEM>>>(
        ch, cl, woh, wol, nullptr, nullptr, nullptr, nullptr, nullptr, nullptr,
        out, bo);
}

// round 16
// speedup vs baseline: 2.1505x; 2.0598x over previous
#include <cuda_runtime.h>
#include <cuda_fp16.h>
#include <math.h>
#include <stdint.h>

#define BATCH 2
#define TSEQ  2048
#define DM    1024
#define NH    16
#define DH    64
#define MTOT  (BATCH*TSEQ)   // 4096

// ---------------- scratch (device globals; no allocation allowed) ----------
__device__ __align__(16) __half g_q[(size_t)BATCH*NH*TSEQ*DH];
__device__ __align__(16) __half g_k[(size_t)BATCH*NH*TSEQ*DH];
__device__ __align__(16) __half g_v[(size_t)BATCH*NH*TSEQ*DH];
__device__ __align__(16) __half g_x16[(size_t)MTOT*DM];
__device__ __align__(16) __half g_w16[(size_t)3*DM*DM];   // [Wk;Wq;Wv] (q<-Wk swap!)
__device__ __align__(16) __half g_c16[(size_t)MTOT*DM];
__device__ __align__(16) __half g_wo16[(size_t)DM*DM];

// ---------------- helpers ---------------------------------------------------
__device__ __forceinline__ uint32_t smem_u32(const void* p) {
    uint32_t a;
    asm("{ .reg .u64 t; cvta.to.shared.u64 t, %1; cvt.u32.u64 %0, t; }"
        : "=r"(a) : "l"(p));
    return a;
}
__device__ __forceinline__ void cp_async16(uint32_t dst, const void* src) {
    asm volatile("cp.async.cg.shared.global [%0], [%1], 16;"
                 :: "r"(dst), "l"(src) : "memory");
}
__device__ __forceinline__ void cp_commit() {
    asm volatile("cp.async.commit_group;" ::: "memory");
}
__device__ __forceinline__ void cp_wait_all() {
    asm volatile("cp.async.wait_group 0;" ::: "memory");
}
__device__ __forceinline__ void cp_wait_1() {
    asm volatile("cp.async.wait_group 1;" ::: "memory");
}
__device__ __forceinline__ void ldsm4(uint32_t* r, uint32_t a) {
    asm volatile("ldmatrix.sync.aligned.m8n8.x4.shared.b16 {%0,%1,%2,%3}, [%4];"
                 : "=r"(r[0]), "=r"(r[1]), "=r"(r[2]), "=r"(r[3]) : "r"(a));
}
__device__ __forceinline__ void ldsm4t(uint32_t* r, uint32_t a) {
    asm volatile("ldmatrix.sync.aligned.m8n8.x4.trans.shared.b16 {%0,%1,%2,%3}, [%4];"
                 : "=r"(r[0]), "=r"(r[1]), "=r"(r[2]), "=r"(r[3]) : "r"(a));
}
__device__ __forceinline__ void mma_f16(float* c, const uint32_t* a, const uint32_t* b) {
    asm volatile(
        "mma.sync.aligned.m16n8k16.row.col.f32.f16.f16.f32 "
        "{%0,%1,%2,%3}, {%4,%5,%6,%7}, {%8,%9}, {%0,%1,%2,%3};"
        : "+f"(c[0]), "+f"(c[1]), "+f"(c[2]), "+f"(c[3])
        : "r"(a[0]), "r"(a[1]), "r"(a[2]), "r"(a[3]), "r"(b[0]), "r"(b[1]));
}
// pack two fp32 -> f16x2 (lo half = v_lo)
__device__ __forceinline__ uint32_t cvth2(float v_hi, float v_lo) {
    uint32_t r;
    asm("cvt.rn.f16x2.f32 %0, %1, %2;" : "=r"(r) : "f"(v_hi), "f"(v_lo));
    return r;
}
__device__ __forceinline__ uint32_t swz(int row, int colb) {
    uint32_t off = row * 128 + colb;
    return off ^ ((off >> 3) & 0x70);
}

// ---------------- merged fp32 -> fp16 convert (5 segments, coarsened) -------
#define XB4 ((MTOT*DM/4)/1024)   // 1024 blocks for x
#define WB4 ((DM*DM/4)/1024)     // 256 blocks per weight

__global__ void __launch_bounds__(256) conv5_kernel(
    const float* __restrict__ x,  const float* __restrict__ Wk,
    const float* __restrict__ Wq, const float* __restrict__ Wv,
    const float* __restrict__ Wo,
    __half* __restrict__ x16, __half* __restrict__ w16,
    __half* __restrict__ wo16)
{
    int blk = blockIdx.x;
    const float* src;
    __half* dst;
    int base4;
    if (blk < XB4) {
        src = x; dst = x16;
        base4 = blk * 1024;
    } else {
        int wseg = (blk - XB4) / WB4;      // 0..3
        int wblk = (blk - XB4) % WB4;
        base4 = wblk * 1024;
        if (wseg == 0)      { src = Wk; dst = w16; }
        else if (wseg == 1) { src = Wq; dst = w16 + DM*DM; }
        else if (wseg == 2) { src = Wv; dst = w16 + 2*DM*DM; }
        else                { src = Wo; dst = wo16; }
    }
#pragma unroll
    for (int r = 0; r < 4; r++) {
        int i = base4 + threadIdx.x + r * 256;
        float4 v = ((const float4*)src)[i];
        uint32_t p0 = cvth2(v.y, v.x);
        uint32_t p1 = cvth2(v.w, v.z);
        *(uint2*)(dst + (size_t)i*4) = make_uint2(p0, p1);
    }
}

// ---------------------------------------------------------------------------
// fp16 single-product GEMM on HMMA. 256 threads, 8 warps (32x64 tile each),
// 3-stage cp.async pipeline (wait_group 1).
// MODE 0: fused QKV -> fp16 head-major (softmax scale folded into q).
// MODE 1: fp32 out + bias.
// ---------------------------------------------------------------------------
#define GK       DM
#define BK       64
#define NCHUNK   (GK/BK)        // 16
#define TILE_B   (128*128)      // 16 KB (128 rows x 64 halves)
#define BUF_B    (2*TILE_B)     // A + B = 32 KB
#define GEMM_SMEM (3*BUF_B)     // 98304

template<int MODE>
__global__ void __launch_bounds__(256, 1) mma_gemm(
    const __half* __restrict__ A, const __half* __restrict__ B,
    __half* __restrict__ q, __half* __restrict__ k, __half* __restrict__ v,
    float* __restrict__ out, const float* __restrict__ bias)
{
    extern __shared__ char smem[];
    const uint32_t sb = smem_u32(smem);
    const int tid  = threadIdx.x;
    const int lane = tid & 31;
    const int w    = tid >> 5;
    const int m0   = blockIdx.y * 128;
    const int n0   = blockIdx.x * 128;

    const __half* srcA = A + (size_t)m0*GK;
    const __half* srcB = B + (size_t)n0*GK;

    auto issue_chunk = [&](int buf, int k0) {
        uint32_t dbase = sb + buf * BUF_B;
#pragma unroll
        for (int r2 = 0; r2 < 4; r2++) {
            int id  = tid + 256 * r2;      // 0..1023
            int row = id >> 3;
            int c16 = id & 7;
            cp_async16(dbase + swz(row, c16*16),
                       srcA + (size_t)row*GK + k0 + c16*8);
            cp_async16(dbase + TILE_B + swz(row, c16*16),
                       srcB + (size_t)row*GK + k0 + c16*8);
        }
        cp_commit();
    };

    float acc[2][8][4];
#pragma unroll
    for (int mt = 0; mt < 2; mt++)
#pragma unroll
        for (int nt = 0; nt < 8; nt++)
#pragma unroll
            for (int e = 0; e < 4; e++) acc[mt][nt][e] = 0.0f;

    const int mr  = (w & 3) * 32;
    const int nc0 = (w >> 2) * 64;
    const int quad = lane >> 3;
    const int l7   = lane & 7;
    const int a_row_off = (quad & 1) * 8 + l7;
    const int a_col_off = (quad >> 1) * 16;
    const int b_row_off = (quad >> 1) * 8 + l7;
    const int b_col_off = (quad & 1) * 16;

    issue_chunk(0, 0);
    issue_chunk(1, BK);

    for (int c = 0; c < NCHUNK; c++) {
        if (c + 1 < NCHUNK) cp_wait_1(); else cp_wait_all();
        __syncthreads();
        if (c + 2 < NCHUNK) issue_chunk((c + 2) % 3, (c + 2) * BK);

        const uint32_t pA = sb + (c % 3) * BUF_B;
        const uint32_t pB = pA + TILE_B;

#pragma unroll
        for (int ks = 0; ks < 4; ks++) {
            const int k0b = ks * 32;
            uint32_t aF[2][4], bF[8][2];
#pragma unroll
            for (int mt = 0; mt < 2; mt++)
                ldsm4(aF[mt], pA + swz(mr + mt*16 + a_row_off, k0b + a_col_off));
#pragma unroll
            for (int ng = 0; ng < 4; ng++) {
                uint32_t t4[4];
                ldsm4(t4, pB + swz(nc0 + ng*16 + b_row_off, k0b + b_col_off));
                bF[ng*2][0] = t4[0]; bF[ng*2][1] = t4[1];
                bF[ng*2+1][0] = t4[2]; bF[ng*2+1][1] = t4[3];
            }
#pragma unroll
            for (int mt = 0; mt < 2; mt++)
#pragma unroll
                for (int nt = 0; nt < 8; nt++) mma_f16(acc[mt][nt], aF[mt], bF[nt]);
        }
    }

    // ---- epilogue ----
#pragma unroll
    for (int mt = 0; mt < 2; mt++) {
#pragma unroll
        for (int half = 0; half < 2; half++) {
            const int m = m0 + mr + mt*16 + (lane >> 2) + half*8;
#pragma unroll
            for (int nt = 0; nt < 8; nt++) {
                const int n = n0 + nc0 + nt*8 + (lane & 3)*2;
                const float c0 = acc[mt][nt][half*2 + 0];
                const float c1 = acc[mt][nt][half*2 + 1];
                if (MODE == 0) {
                    const int bb  = m >> 11;
                    const int t   = m & 2047;
                    const int mat = n >> 10;
                    const int np  = n & 1023;
                    const float sc = (mat == 0) ? 0.125f : 1.0f;
                    uint32_t hp = cvth2(c1*sc, c0*sc);
                    __half* dst = (mat == 0) ? q : ((mat == 1) ? k : v);
                    size_t idx = ((size_t)(bb*NH + (np >> 6)) * TSEQ + t) * DH + (np & 63);
                    *(uint32_t*)(dst + idx) = hp;
                } else {
                    const float2 bv = *(const float2*)(bias + n);
                    *(float2*)(out + (size_t)m * DM + n) =
                        make_float2(c0 + bv.x, c1 + bv.y);
                }
            }
        }
    }
}

// ---------------------------------------------------------------------------
// Causal flash attention on fp16 HMMA (single product). 128 queries/block,
// 8 warps, 64-key chunks, 3-stage KV pipeline, longest-first scheduling.
// ---------------------------------------------------------------------------
#define AKV   8192                      // 64 keys x 128B
#define ABUF  (2*AKV)                   // K + V = 16 KB per stage
#define AQ_OFF (3*ABUF)                 // Q after 3 KV stages
#define ATTN_SMEM (3*ABUF + 16384)      // 65536

__global__ void __launch_bounds__(256, 1) attn_mma(
    const __half* __restrict__ q_g, const __half* __restrict__ k_g,
    const __half* __restrict__ v_g, __half* __restrict__ c_g)
{
    extern __shared__ char smem[];
    const uint32_t sb = smem_u32(smem);
    const int tid  = threadIdx.x;
    const int lane = tid & 31;
    const int w    = tid >> 5;
    const int qt   = (TSEQ/128 - 1) - blockIdx.x;   // longest blocks first
    const int bh   = blockIdx.y;
    const int g    = lane >> 2;
    const int tig  = lane & 3;
    const int quad = lane >> 3;
    const int l7   = lane & 7;
    const int a_row  = (quad & 1) * 8 + l7;
    const int a_colb = (quad >> 1) * 16;
    const int b_row  = (quad >> 1) * 8 + l7;
    const int b_colb = (quad & 1) * 16;
    const int v_row  = (quad & 1) * 8 + l7;
    const int v_colb = (quad >> 1) * 16;

    const size_t base = (size_t)bh * TSEQ * DH;
    const int rowbase = qt * 128 + w * 16;

    auto issue_kv = [&](int buf, int key0) {
        uint32_t db = sb + buf * ABUF;
#pragma unroll
        for (int r = 0; r < 2; r++) {
            int id  = tid + 256 * r;       // 0..511
            int row = id >> 3;
            int c16 = id & 7;
            cp_async16(db + swz(row, c16*16),
                       k_g + base + (size_t)(key0 + row)*DH + c16*8);
            cp_async16(db + AKV + swz(row, c16*16),
                       v_g + base + (size_t)(key0 + row)*DH + c16*8);
        }
        cp_commit();
    };

    const int NKT = 2*qt + 2;

    // prologue: group0 = Q + KV chunk 0; group1 = KV chunk 1
#pragma unroll
    for (int r = 0; r < 4; r++) {
        int id  = tid + 256 * r;
        int row = id >> 3;
        int c16 = id & 7;
        cp_async16(sb + AQ_OFF + swz(row, c16*16),
                   q_g + base + (size_t)(qt*128 + row)*DH + c16*8);
    }
    issue_kv(0, 0);
    issue_kv(1, 64);

    float s[8][4], o[8][4];
    float m_i[2] = {-1e30f, -1e30f}, l_i[2] = {0.0f, 0.0f};
#pragma unroll
    for (int nt = 0; nt < 8; nt++)
#pragma unroll
        for (int e = 0; e < 4; e++) o[nt][e] = 0.0f;
    uint32_t qf[4][4];

    for (int c = 0; c < NKT; c++) {
        if (c + 1 < NKT) cp_wait_1(); else cp_wait_all();
        __syncthreads();
        if (c == 0) {
#pragma unroll
            for (int ks = 0; ks < 4; ks++)
                ldsm4(qf[ks], sb + AQ_OFF + swz(w*16 + a_row, ks*32 + a_colb));
        }
        if (c + 2 < NKT) issue_kv((c + 2) % 3, (c + 2) * 64);

        const int key0 = c * 64;
        if (key0 <= rowbase + 15) {
            const uint32_t pb = sb + (c % 3) * ABUF;

            // ---- S = Q K^T (single fp16 product) ----
#pragma unroll
            for (int nt = 0; nt < 8; nt++)
#pragma unroll
                for (int e = 0; e < 4; e++) s[nt][e] = 0.0f;
#pragma unroll
            for (int ks = 0; ks < 4; ks++) {
                uint32_t bK[8][2], t4[4];
#pragma unroll
                for (int ng = 0; ng < 4; ng++) {
                    ldsm4(t4, pb + swz(ng*16 + b_row, ks*32 + b_colb));
                    bK[ng*2][0] = t4[0]; bK[ng*2][1] = t4[1];
                    bK[ng*2+1][0] = t4[2]; bK[ng*2+1][1] = t4[3];
                }
#pragma unroll
                for (int nt = 0; nt < 8; nt++) mma_f16(s[nt], qf[ks], bK[nt]);
            }

            // ---- causal mask (diagonal chunks only) ----
            if (key0 + 63 > rowbase) {
#pragma unroll
                for (int nt = 0; nt < 8; nt++) {
#pragma unroll
                    for (int e = 0; e < 4; e++) {
                        int col = key0 + nt*8 + 2*tig + (e & 1);
                        int row = rowbase + g + ((e >= 2) ? 8 : 0);
                        if (col > row) s[nt][e] = -1e30f;
                    }
                }
            }

            // ---- online softmax ----
            float rm0 = -1e30f, rm1 = -1e30f;
#pragma unroll
            for (int nt = 0; nt < 8; nt++) {
                rm0 = fmaxf(rm0, fmaxf(s[nt][0], s[nt][1]));
                rm1 = fmaxf(rm1, fmaxf(s[nt][2], s[nt][3]));
            }
            rm0 = fmaxf(rm0, __shfl_xor_sync(0xffffffffu, rm0, 1));
            rm0 = fmaxf(rm0, __shfl_xor_sync(0xffffffffu, rm0, 2));
            rm1 = fmaxf(rm1, __shfl_xor_sync(0xffffffffu, rm1, 1));
            rm1 = fmaxf(rm1, __shfl_xor_sync(0xffffffffu, rm1, 2));
            float mn0 = fmaxf(m_i[0], rm0), mn1 = fmaxf(m_i[1], rm1);
            float al0 = __expf(m_i[0] - mn0), al1 = __expf(m_i[1] - mn1);
            m_i[0] = mn0; m_i[1] = mn1;
            float rs0 = 0.0f, rs1 = 0.0f;
#pragma unroll
            for (int nt = 0; nt < 8; nt++) {
                s[nt][0] = __expf(s[nt][0] - mn0);
                s[nt][1] = __expf(s[nt][1] - mn0);
                s[nt][2] = __expf(s[nt][2] - mn1);
                s[nt][3] = __expf(s[nt][3] - mn1);
                rs0 += s[nt][0] + s[nt][1];
                rs1 += s[nt][2] + s[nt][3];
            }
            rs0 += __shfl_xor_sync(0xffffffffu, rs0, 1);
            rs0 += __shfl_xor_sync(0xffffffffu, rs0, 2);
            rs1 += __shfl_xor_sync(0xffffffffu, rs1, 1);
            rs1 += __shfl_xor_sync(0xffffffffu, rs1, 2);
            l_i[0] = l_i[0]*al0 + rs0;
            l_i[1] = l_i[1]*al1 + rs1;
#pragma unroll
            for (int nt = 0; nt < 8; nt++) {
                o[nt][0] *= al0; o[nt][1] *= al0;
                o[nt][2] *= al1; o[nt][3] *= al1;
            }

            // ---- O += P V (single fp16 product) ----
#pragma unroll
            for (int ks = 0; ks < 4; ks++) {
                uint32_t ph[4];
                ph[0] = cvth2(s[2*ks][1],   s[2*ks][0]);
                ph[1] = cvth2(s[2*ks][3],   s[2*ks][2]);
                ph[2] = cvth2(s[2*ks+1][1], s[2*ks+1][0]);
                ph[3] = cvth2(s[2*ks+1][3], s[2*ks+1][2]);
                uint32_t bV[8][2], t4[4];
#pragma unroll
                for (int ng = 0; ng < 4; ng++) {
                    ldsm4t(t4, pb + AKV + swz(ks*16 + v_row, ng*32 + v_colb));
                    bV[ng*2][0] = t4[0]; bV[ng*2][1] = t4[1];
                    bV[ng*2+1][0] = t4[2]; bV[ng*2+1][1] = t4[3];
                }
#pragma unroll
                for (int nt = 0; nt < 8; nt++) mma_f16(o[nt], ph, bV[nt]);
            }
        }
    }

    // ---- epilogue: ctx as fp16 into c_g [m][1024] ----
    const int b_ = bh >> 4;
    const int h  = bh & 15;
    const float inv0 = 1.0f / l_i[0];
    const float inv1 = 1.0f / l_i[1];
    const int t0r = rowbase + g;
    const int t1r = rowbase + g + 8;
#pragma unroll
    for (int nt = 0; nt < 8; nt++) {
        const int col = h*64 + nt*8 + 2*tig;
        size_t i0 = ((size_t)(b_*TSEQ) + t0r) * DM + col;
        *(uint32_t*)(c_g + i0) = cvth2(o[nt][1]*inv0, o[nt][0]*inv0);
        size_t i1 = ((size_t)(b_*TSEQ) + t1r) * DM + col;
        *(uint32_t*)(c_g + i1) = cvth2(o[nt][3]*inv1, o[nt][2]*inv1);
    }
}

// ---------------------------------------------------------------------------
extern "C" void kernel_launch(void* const* d_in, const int* in_sizes, int n_in,
                              void* d_out, int out_size)
{
    const float* x  = (const float*)d_in[0];
    const float* Wq = (const float*)d_in[1];
    const float* Wk = (const float*)d_in[2];
    const float* Wv = (const float*)d_in[3];
    const float* Wo = (const float*)d_in[4];
    const float* bo = (const float*)d_in[5];
    float* out = (float*)d_out;

    __half *q, *k, *v, *x16, *w16, *c16, *wo16;
    cudaGetSymbolAddress((void**)&q,    g_q);
    cudaGetSymbolAddress((void**)&k,    g_k);
    cudaGetSymbolAddress((void**)&v,    g_v);
    cudaGetSymbolAddress((void**)&x16,  g_x16);
    cudaGetSymbolAddress((void**)&w16,  g_w16);
    cudaGetSymbolAddress((void**)&c16,  g_c16);
    cudaGetSymbolAddress((void**)&wo16, g_wo16);

    cudaFuncSetAttribute(mma_gemm<0>,
                         cudaFuncAttributeMaxDynamicSharedMemorySize, GEMM_SMEM);
    cudaFuncSetAttribute(mma_gemm<1>,
                         cudaFuncAttributeMaxDynamicSharedMemorySize, GEMM_SMEM);
    cudaFuncSetAttribute(attn_mma,
                         cudaFuncAttributeMaxDynamicSharedMemorySize, ATTN_SMEM);

    // single merged convert launch (reference swaps names: q = x@Wk^T, k = x@Wq^T)
    conv5_kernel<<<XB4 + 4*WB4, 256>>>(x, Wk, Wq, Wv, Wo, x16, w16, wo16);

    // fused QKV projection (N=3072), fp16 epilogue
    mma_gemm<0><<<dim3(3*DM/128, MTOT/128), 256, GEMM_SMEM>>>(
        x16, w16, q, k, v, nullptr, nullptr);

    attn_mma<<<dim3(TSEQ/128, BATCH*NH), 256, ATTN_SMEM>>>(q, k, v, c16);

    mma_gemm<1><<<dim3(DM/128, MTOT/128), 256, GEMM_SMEM>>>(
        c16, wo16, nullptr, nullptr, nullptr, out, bo);
}

// round 17
// speedup vs baseline: 2.2540x; 1.0482x over previous
#include <cuda_runtime.h>
#include <cuda_fp16.h>
#include <math.h>
#include <stdint.h>

#define BATCH 2
#define TSEQ  2048
#define DM    1024
#define NH    16
#define DH    64
#define MTOT  (BATCH*TSEQ)   // 4096

// ---------------- scratch (device globals; no allocation allowed) ----------
__device__ __align__(16) __half g_q[(size_t)BATCH*NH*TSEQ*DH];
__device__ __align__(16) __half g_k[(size_t)BATCH*NH*TSEQ*DH];
__device__ __align__(16) __half g_v[(size_t)BATCH*NH*TSEQ*DH];
__device__ __align__(16) __half g_x16[(size_t)MTOT*DM];
__device__ __align__(16) __half g_w16[(size_t)3*DM*DM];   // [Wk;Wq;Wv] (q<-Wk swap!)
__device__ __align__(16) __half g_c16[(size_t)MTOT*DM];
__device__ __align__(16) __half g_wo16[(size_t)DM*DM];

// ---------------- helpers ---------------------------------------------------
__device__ __forceinline__ uint32_t smem_u32(const void* p) {
    uint32_t a;
    asm("{ .reg .u64 t; cvta.to.shared.u64 t, %1; cvt.u32.u64 %0, t; }"
        : "=r"(a) : "l"(p));
    return a;
}
__device__ __forceinline__ void cp_async16(uint32_t dst, const void* src) {
    asm volatile("cp.async.cg.shared.global [%0], [%1], 16;"
                 :: "r"(dst), "l"(src) : "memory");
}
__device__ __forceinline__ void cp_commit() {
    asm volatile("cp.async.commit_group;" ::: "memory");
}
__device__ __forceinline__ void cp_wait_all() {
    asm volatile("cp.async.wait_group 0;" ::: "memory");
}
__device__ __forceinline__ void cp_wait_1() {
    asm volatile("cp.async.wait_group 1;" ::: "memory");
}
__device__ __forceinline__ void ldsm4(uint32_t* r, uint32_t a) {
    asm volatile("ldmatrix.sync.aligned.m8n8.x4.shared.b16 {%0,%1,%2,%3}, [%4];"
                 : "=r"(r[0]), "=r"(r[1]), "=r"(r[2]), "=r"(r[3]) : "r"(a));
}
__device__ __forceinline__ void ldsm4t(uint32_t* r, uint32_t a) {
    asm volatile("ldmatrix.sync.aligned.m8n8.x4.trans.shared.b16 {%0,%1,%2,%3}, [%4];"
                 : "=r"(r[0]), "=r"(r[1]), "=r"(r[2]), "=r"(r[3]) : "r"(a));
}
__device__ __forceinline__ void mma_f16(float* c, const uint32_t* a, const uint32_t* b) {
    asm volatile(
        "mma.sync.aligned.m16n8k16.row.col.f32.f16.f16.f32 "
        "{%0,%1,%2,%3}, {%4,%5,%6,%7}, {%8,%9}, {%0,%1,%2,%3};"
        : "+f"(c[0]), "+f"(c[1]), "+f"(c[2]), "+f"(c[3])
        : "r"(a[0]), "r"(a[1]), "r"(a[2]), "r"(a[3]), "r"(b[0]), "r"(b[1]));
}
__device__ __forceinline__ uint32_t cvth2(float v_hi, float v_lo) {
    uint32_t r;
    asm("cvt.rn.f16x2.f32 %0, %1, %2;" : "=r"(r) : "f"(v_hi), "f"(v_lo));
    return r;
}
__device__ __forceinline__ uint32_t swz(int row, int colb) {
    uint32_t off = row * 128 + colb;
    return off ^ ((off >> 3) & 0x70);
}

// ---------------- merged fp32 -> fp16 convert (5 segments, coarsened) -------
#define XB4 ((MTOT*DM/4)/1024)   // 1024 blocks for x
#define WB4 ((DM*DM/4)/1024)     // 256 blocks per weight

__global__ void __launch_bounds__(256) conv5_kernel(
    const float* __restrict__ x,  const float* __restrict__ Wk,
    const float* __restrict__ Wq, const float* __restrict__ Wv,
    const float* __restrict__ Wo,
    __half* __restrict__ x16, __half* __restrict__ w16,
    __half* __restrict__ wo16)
{
    int blk = blockIdx.x;
    const float* src;
    __half* dst;
    int base4;
    if (blk < XB4) {
        src = x; dst = x16;
        base4 = blk * 1024;
    } else {
        int wseg = (blk - XB4) / WB4;      // 0..3
        int wblk = (blk - XB4) % WB4;
        base4 = wblk * 1024;
        if (wseg == 0)      { src = Wk; dst = w16; }
        else if (wseg == 1) { src = Wq; dst = w16 + DM*DM; }
        else if (wseg == 2) { src = Wv; dst = w16 + 2*DM*DM; }
        else                { src = Wo; dst = wo16; }
    }
#pragma unroll
    for (int r = 0; r < 4; r++) {
        int i = base4 + threadIdx.x + r * 256;
        float4 v = ((const float4*)src)[i];
        uint32_t p0 = cvth2(v.y, v.x);
        uint32_t p1 = cvth2(v.w, v.z);
        *(uint2*)(dst + (size_t)i*4) = make_uint2(p0, p1);
    }
}

// ---------------------------------------------------------------------------
// fp16 single-product GEMM on HMMA. 256 threads, 8 warps (32x64 tile each).
// BK=128 (8 chunks) -> per-chunk fixed overhead halved vs BK=64. Each 32 KB
// operand chunk = two 16 KB k-sub-tiles (keeps 128B-row SW128 swizzle).
// 3-stage cp.async pipeline (wait_group 1), 192 KB smem.
// MODE 0: fused QKV -> fp16 head-major (softmax scale folded into q).
// MODE 1: fp32 out + bias.
// ---------------------------------------------------------------------------
#define GK       DM
#define BK       128
#define NCHUNK   (GK/BK)        // 8
#define SUB_B    (128*128)      // 16 KB k-sub-tile (128 rows x 64 halves)
#define TILE_B   (2*SUB_B)      // 32 KB per operand per chunk
#define BUF_B    (2*TILE_B)     // A + B = 64 KB per stage
#define GEMM_SMEM (3*BUF_B)     // 196608

template<int MODE>
__global__ void __launch_bounds__(256, 1) mma_gemm(
    const __half* __restrict__ A, const __half* __restrict__ B,
    __half* __restrict__ q, __half* __restrict__ k, __half* __restrict__ v,
    float* __restrict__ out, const float* __restrict__ bias)
{
    extern __shared__ char smem[];
    const uint32_t sb = smem_u32(smem);
    const int tid  = threadIdx.x;
    const int lane = tid & 31;
    const int w    = tid >> 5;
    const int m0   = blockIdx.y * 128;
    const int n0   = blockIdx.x * 128;

    const __half* srcA = A + (size_t)m0*GK;
    const __half* srcB = B + (size_t)n0*GK;

    auto issue_chunk = [&](int buf, int k0) {
        uint32_t dbase = sb + buf * BUF_B;
#pragma unroll
        for (int sub = 0; sub < 2; sub++) {
#pragma unroll
            for (int r2 = 0; r2 < 4; r2++) {
                int id  = tid + 256 * r2;      // 0..1023
                int row = id >> 3;
                int c16 = id & 7;
                uint32_t so = sub * SUB_B + swz(row, c16*16);
                size_t   go = (size_t)row*GK + k0 + sub*64 + c16*8;
                cp_async16(dbase + so,          srcA + go);
                cp_async16(dbase + TILE_B + so, srcB + go);
            }
        }
        cp_commit();
    };

    float acc[2][8][4];
#pragma unroll
    for (int mt = 0; mt < 2; mt++)
#pragma unroll
        for (int nt = 0; nt < 8; nt++)
#pragma unroll
            for (int e = 0; e < 4; e++) acc[mt][nt][e] = 0.0f;

    const int mr  = (w & 3) * 32;
    const int nc0 = (w >> 2) * 64;
    const int quad = lane >> 3;
    const int l7   = lane & 7;
    const int a_row_off = (quad & 1) * 8 + l7;
    const int a_col_off = (quad >> 1) * 16;
    const int b_row_off = (quad >> 1) * 8 + l7;
    const int b_col_off = (quad & 1) * 16;

    issue_chunk(0, 0);
    issue_chunk(1, BK);

    for (int c = 0; c < NCHUNK; c++) {
        if (c + 1 < NCHUNK) cp_wait_1(); else cp_wait_all();
        __syncthreads();
        if (c + 2 < NCHUNK) issue_chunk((c + 2) % 3, (c + 2) * BK);

        const uint32_t pA = sb + (c % 3) * BUF_B;
        const uint32_t pB = pA + TILE_B;

#pragma unroll
        for (int ks = 0; ks < 8; ks++) {
            const uint32_t subo = (ks >> 2) * SUB_B;
            const int k0b = (ks & 3) * 32;
            uint32_t aF[2][4], bF[8][2];
#pragma unroll
            for (int mt = 0; mt < 2; mt++)
                ldsm4(aF[mt], pA + subo + swz(mr + mt*16 + a_row_off, k0b + a_col_off));
#pragma unroll
            for (int ng = 0; ng < 4; ng++) {
                uint32_t t4[4];
                ldsm4(t4, pB + subo + swz(nc0 + ng*16 + b_row_off, k0b + b_col_off));
                bF[ng*2][0] = t4[0]; bF[ng*2][1] = t4[1];
                bF[ng*2+1][0] = t4[2]; bF[ng*2+1][1] = t4[3];
            }
#pragma unroll
            for (int mt = 0; mt < 2; mt++)
#pragma unroll
                for (int nt = 0; nt < 8; nt++) mma_f16(acc[mt][nt], aF[mt], bF[nt]);
        }
    }

    // ---- epilogue ----
#pragma unroll
    for (int mt = 0; mt < 2; mt++) {
#pragma unroll
        for (int half = 0; half < 2; half++) {
            const int m = m0 + mr + mt*16 + (lane >> 2) + half*8;
#pragma unroll
            for (int nt = 0; nt < 8; nt++) {
                const int n = n0 + nc0 + nt*8 + (lane & 3)*2;
                const float c0 = acc[mt][nt][half*2 + 0];
                const float c1 = acc[mt][nt][half*2 + 1];
                if (MODE == 0) {
                    const int bb  = m >> 11;
                    const int t   = m & 2047;
                    const int mat = n >> 10;
                    const int np  = n & 1023;
                    const float sc = (mat == 0) ? 0.125f : 1.0f;
                    uint32_t hp = cvth2(c1*sc, c0*sc);
                    __half* dst = (mat == 0) ? q : ((mat == 1) ? k : v);
                    size_t idx = ((size_t)(bb*NH + (np >> 6)) * TSEQ + t) * DH + (np & 63);
                    *(uint32_t*)(dst + idx) = hp;
                } else {
                    const float2 bv = *(const float2*)(bias + n);
                    *(float2*)(out + (size_t)m * DM + n) =
                        make_float2(c0 + bv.x, c1 + bv.y);
                }
            }
        }
    }
}

// ---------------------------------------------------------------------------
// Causal flash attention on fp16 HMMA (single product) — unchanged from the
// passing round-16 kernel. 128 queries/block, 8 warps, 64-key chunks,
// 3-stage KV pipeline, longest-first scheduling.
// ---------------------------------------------------------------------------
#define AKV   8192                      // 64 keys x 128B
#define ABUF  (2*AKV)                   // K + V = 16 KB per stage
#define AQ_OFF (3*ABUF)                 // Q after 3 KV stages
#define ATTN_SMEM (3*ABUF + 16384)      // 65536

__global__ void __launch_bounds__(256, 1) attn_mma(
    const __half* __restrict__ q_g, const __half* __restrict__ k_g,
    const __half* __restrict__ v_g, __half* __restrict__ c_g)
{
    extern __shared__ char smem[];
    const uint32_t sb = smem_u32(smem);
    const int tid  = threadIdx.x;
    const int lane = tid & 31;
    const int w    = tid >> 5;
    const int qt   = (TSEQ/128 - 1) - blockIdx.x;   // longest blocks first
    const int bh   = blockIdx.y;
    const int g    = lane >> 2;
    const int tig  = lane & 3;
    const int quad = lane >> 3;
    const int l7   = lane & 7;
    const int a_row  = (quad & 1) * 8 + l7;
    const int a_colb = (quad >> 1) * 16;
    const int b_row  = (quad >> 1) * 8 + l7;
    const int b_colb = (quad & 1) * 16;
    const int v_row  = (quad & 1) * 8 + l7;
    const int v_colb = (quad >> 1) * 16;

    const size_t base = (size_t)bh * TSEQ * DH;
    const int rowbase = qt * 128 + w * 16;

    auto issue_kv = [&](int buf, int key0) {
        uint32_t db = sb + buf * ABUF;
#pragma unroll
        for (int r = 0; r < 2; r++) {
            int id  = tid + 256 * r;       // 0..511
            int row = id >> 3;
            int c16 = id & 7;
            cp_async16(db + swz(row, c16*16),
                       k_g + base + (size_t)(key0 + row)*DH + c16*8);
            cp_async16(db + AKV + swz(row, c16*16),
                       v_g + base + (size_t)(key0 + row)*DH + c16*8);
        }
        cp_commit();
    };

    const int NKT = 2*qt + 2;

#pragma unroll
    for (int r = 0; r < 4; r++) {
        int id  = tid + 256 * r;
        int row = id >> 3;
        int c16 = id & 7;
        cp_async16(sb + AQ_OFF + swz(row, c16*16),
                   q_g + base + (size_t)(qt*128 + row)*DH + c16*8);
    }
    issue_kv(0, 0);
    issue_kv(1, 64);

    float s[8][4], o[8][4];
    float m_i[2] = {-1e30f, -1e30f}, l_i[2] = {0.0f, 0.0f};
#pragma unroll
    for (int nt = 0; nt < 8; nt++)
#pragma unroll
        for (int e = 0; e < 4; e++) o[nt][e] = 0.0f;
    uint32_t qf[4][4];

    for (int c = 0; c < NKT; c++) {
        if (c + 1 < NKT) cp_wait_1(); else cp_wait_all();
        __syncthreads();
        if (c == 0) {
#pragma unroll
            for (int ks = 0; ks < 4; ks++)
                ldsm4(qf[ks], sb + AQ_OFF + swz(w*16 + a_row, ks*32 + a_colb));
        }
        if (c + 2 < NKT) issue_kv((c + 2) % 3, (c + 2) * 64);

        const int key0 = c * 64;
        if (key0 <= rowbase + 15) {
            const uint32_t pb = sb + (c % 3) * ABUF;

            // ---- S = Q K^T ----
#pragma unroll
            for (int nt = 0; nt < 8; nt++)
#pragma unroll
                for (int e = 0; e < 4; e++) s[nt][e] = 0.0f;
#pragma unroll
            for (int ks = 0; ks < 4; ks++) {
                uint32_t bK[8][2], t4[4];
#pragma unroll
                for (int ng = 0; ng < 4; ng++) {
                    ldsm4(t4, pb + swz(ng*16 + b_row, ks*32 + b_colb));
                    bK[ng*2][0] = t4[0]; bK[ng*2][1] = t4[1];
                    bK[ng*2+1][0] = t4[2]; bK[ng*2+1][1] = t4[3];
                }
#pragma unroll
                for (int nt = 0; nt < 8; nt++) mma_f16(s[nt], qf[ks], bK[nt]);
            }

            // ---- causal mask (diagonal chunks only) ----
            if (key0 + 63 > rowbase) {
#pragma unroll
                for (int nt = 0; nt < 8; nt++) {
#pragma unroll
                    for (int e = 0; e < 4; e++) {
                        int col = key0 + nt*8 + 2*tig + (e & 1);
                        int row = rowbase + g + ((e >= 2) ? 8 : 0);
                        if (col > row) s[nt][e] = -1e30f;
                    }
                }
            }

            // ---- online softmax ----
            float rm0 = -1e30f, rm1 = -1e30f;
#pragma unroll
            for (int nt = 0; nt < 8; nt++) {
                rm0 = fmaxf(rm0, fmaxf(s[nt][0], s[nt][1]));
                rm1 = fmaxf(rm1, fmaxf(s[nt][2], s[nt][3]));
            }
            rm0 = fmaxf(rm0, __shfl_xor_sync(0xffffffffu, rm0, 1));
            rm0 = fmaxf(rm0, __shfl_xor_sync(0xffffffffu, rm0, 2));
            rm1 = fmaxf(rm1, __shfl_xor_sync(0xffffffffu, rm1, 1));
            rm1 = fmaxf(rm1, __shfl_xor_sync(0xffffffffu, rm1, 2));
            float mn0 = fmaxf(m_i[0], rm0), mn1 = fmaxf(m_i[1], rm1);
            float al0 = __expf(m_i[0] - mn0), al1 = __expf(m_i[1] - mn1);
            m_i[0] = mn0; m_i[1] = mn1;
            float rs0 = 0.0f, rs1 = 0.0f;
#pragma unroll
            for (int nt = 0; nt < 8; nt++) {
                s[nt][0] = __expf(s[nt][0] - mn0);
                s[nt][1] = __expf(s[nt][1] - mn0);
                s[nt][2] = __expf(s[nt][2] - mn1);
                s[nt][3] = __expf(s[nt][3] - mn1);
                rs0 += s[nt][0] + s[nt][1];
                rs1 += s[nt][2] + s[nt][3];
            }
            rs0 += __shfl_xor_sync(0xffffffffu, rs0, 1);
            rs0 += __shfl_xor_sync(0xffffffffu, rs0, 2);
            rs1 += __shfl_xor_sync(0xffffffffu, rs1, 1);
            rs1 += __shfl_xor_sync(0xffffffffu, rs1, 2);
            l_i[0] = l_i[0]*al0 + rs0;
            l_i[1] = l_i[1]*al1 + rs1;
#pragma unroll
            for (int nt = 0; nt < 8; nt++) {
                o[nt][0] *= al0; o[nt][1] *= al0;
                o[nt][2] *= al1; o[nt][3] *= al1;
            }

            // ---- O += P V ----
#pragma unroll
            for (int ks = 0; ks < 4; ks++) {
                uint32_t ph[4];
                ph[0] = cvth2(s[2*ks][1],   s[2*ks][0]);
                ph[1] = cvth2(s[2*ks][3],   s[2*ks][2]);
                ph[2] = cvth2(s[2*ks+1][1], s[2*ks+1][0]);
                ph[3] = cvth2(s[2*ks+1][3], s[2*ks+1][2]);
                uint32_t bV[8][2], t4[4];
#pragma unroll
                for (int ng = 0; ng < 4; ng++) {
                    ldsm4t(t4, pb + AKV + swz(ks*16 + v_row, ng*32 + v_colb));
                    bV[ng*2][0] = t4[0]; bV[ng*2][1] = t4[1];
                    bV[ng*2+1][0] = t4[2]; bV[ng*2+1][1] = t4[3];
                }
#pragma unroll
                for (int nt = 0; nt < 8; nt++) mma_f16(o[nt], ph, bV[nt]);
            }
        }
    }

    // ---- epilogue: ctx as fp16 into c_g [m][1024] ----
    const int b_ = bh >> 4;
    const int h  = bh & 15;
    const float inv0 = 1.0f / l_i[0];
    const float inv1 = 1.0f / l_i[1];
    const int t0r = rowbase + g;
    const int t1r = rowbase + g + 8;
#pragma unroll
    for (int nt = 0; nt < 8; nt++) {
        const int col = h*64 + nt*8 + 2*tig;
        size_t i0 = ((size_t)(b_*TSEQ) + t0r) * DM + col;
        *(uint32_t*)(c_g + i0) = cvth2(o[nt][1]*inv0, o[nt][0]*inv0);
        size_t i1 = ((size_t)(b_*TSEQ) + t1r) * DM + col;
        *(uint32_t*)(c_g + i1) = cvth2(o[nt][3]*inv1, o[nt][2]*inv1);
    }
}

// ---------------------------------------------------------------------------
extern "C" void kernel_launch(void* const* d_in, const int* in_sizes, int n_in,
                              void* d_out, int out_size)
{
    const float* x  = (const float*)d_in[0];
    const float* Wq = (const float*)d_in[1];
    const float* Wk = (const float*)d_in[2];
    const float* Wv = (const float*)d_in[3];
    const float* Wo = (const float*)d_in[4];
    const float* bo = (const float*)d_in[5];
    float* out = (float*)d_out;

    __half *q, *k, *v, *x16, *w16, *c16, *wo16;
    cudaGetSymbolAddress((void**)&q,    g_q);
    cudaGetSymbolAddress((void**)&k,    g_k);
    cudaGetSymbolAddress((void**)&v,    g_v);
    cudaGetSymbolAddress((void**)&x16,  g_x16);
    cudaGetSymbolAddress((void**)&w16,  g_w16);
    cudaGetSymbolAddress((void**)&c16,  g_c16);
    cudaGetSymbolAddress((void**)&wo16, g_wo16);

    cudaFuncSetAttribute(mma_gemm<0>,
                         cudaFuncAttributeMaxDynamicSharedMemorySize, GEMM_SMEM);
    cudaFuncSetAttribute(mma_gemm<1>,
                         cudaFuncAttributeMaxDynamicSharedMemorySize, GEMM_SMEM);
    cudaFuncSetAttribute(attn_mma,
                         cudaFuncAttributeMaxDynamicSharedMemorySize, ATTN_SMEM);

    // single merged convert launch (reference swaps names: q = x@Wk^T, k = x@Wq^T)
    conv5_kernel<<<XB4 + 4*WB4, 256>>>(x, Wk, Wq, Wv, Wo, x16, w16, wo16);

    // fused QKV projection (N=3072), fp16 epilogue
    mma_gemm<0><<<dim3(3*DM/128, MTOT/128), 256, GEMM_SMEM>>>(
        x16, w16, q, k, v, nullptr, nullptr);

    attn_mma<<<dim3(TSEQ/128, BATCH*NH), 256, ATTN_SMEM>>>(q, k, v, c16);

    mma_gemm<1><<<dim3(DM/128, MTOT/128), 256, GEMM_SMEM>>>(
        c16, wo16, nullptr, nullptr, nullptr, out, bo);
}